// round 9
// baseline (speedup 1.0000x reference)
#include <cuda_runtime.h>
#include <cuda_fp16.h>
#include <cstdint>
#include <math.h>

#define NMAX 20000
#define EMAX 320000
#define D 512

// ---------------- scratch (static device globals; no allocation) -------------
__device__ float  g_H  [NMAX * D];
__device__ float  g_F  [NMAX * D];
__device__ __half g_H16[NMAX * D];
__device__ __half g_R16[NMAX * D];
__device__ float  g_WB [5 * D * D];     // tf32-rounded weights, ALL [N][K] K-major
__device__ float  g_norm[NMAX];
__device__ int    g_cnt [NMAX];
__device__ int    g_off [NMAX + 1];
__device__ int    g_cur [NMAX + 1];
__device__ int    g_csr [EMAX];

// ---------------- side stream + events (created pre-baseline) -----------------
struct SideStream {
    cudaStream_t s2;
    cudaEvent_t  evF, evJ;
    SideStream() {
        cudaFree(0);   // init context early
        cudaStreamCreateWithFlags(&s2, cudaStreamNonBlocking);
        cudaEventCreateWithFlags(&evF, cudaEventDisableTiming);
        cudaEventCreateWithFlags(&evJ, cudaEventDisableTiming);
    }
};
static SideStream g_ss;

// ================= small helpers ==============================================
__device__ __forceinline__ unsigned f2tf(float x)
{
    unsigned r;
    asm("cvt.rna.tf32.f32 %0, %1;" : "=r"(r) : "f"(x));
    return r;
}
__device__ __forceinline__ float rndtf(float x) { return __uint_as_float(f2tf(x)); }

__device__ __forceinline__ void cp16(uint32_t dst, const float* src, int bytes)
{
    asm volatile("cp.async.cg.shared.global [%0], [%1], 16, %2;"
                 :: "r"(dst), "l"(src), "r"(bytes));
}
__device__ __forceinline__ void cp_commit() { asm volatile("cp.async.commit_group;"); }
template <int N> __device__ __forceinline__ void cp_wait()
{ asm volatile("cp.async.wait_group %0;" :: "n"(N)); }

__device__ __forceinline__ void mma8(float* c,
                                     unsigned a0, unsigned a1, unsigned a2, unsigned a3,
                                     unsigned b0, unsigned b1)
{
    asm volatile(
        "mma.sync.aligned.m16n8k8.row.col.f32.tf32.tf32.f32 "
        "{%0,%1,%2,%3},{%4,%5,%6,%7},{%8,%9},{%0,%1,%2,%3};"
        : "+f"(c[0]), "+f"(c[1]), "+f"(c[2]), "+f"(c[3])
        : "r"(a0), "r"(a1), "r"(a2), "r"(a3), "r"(b0), "r"(b1));
}

__device__ __forceinline__ void ldsm4(unsigned& r0, unsigned& r1, unsigned& r2, unsigned& r3,
                                      uint32_t addr)
{
    asm volatile("ldmatrix.sync.aligned.m8n8.x4.shared.b16 {%0,%1,%2,%3}, [%4];"
                 : "=r"(r0), "=r"(r1), "=r"(r2), "=r"(r3) : "r"(addr));
}

// ================= weight prep ===============================================
__global__ void prep_fc(const float* __restrict__ fcw, float* __restrict__ wb)
{
    int i = blockIdx.x * blockDim.x + threadIdx.x;
    if (i < D * D) wb[i] = rndtf(fcw[i]);
}

__global__ void prep_wT(const float* __restrict__ w11, const float* __restrict__ w21,
                        const float* __restrict__ w12, const float* __restrict__ w22,
                        float* __restrict__ wb)
{
    __shared__ float tile[32][33];
    int mat = blockIdx.z;
    const float* s;
    float sc = 1.0f;
    if      (mat == 0)  s = w11;
    else if (mat == 1) { s = w21; sc = 0.1f; }
    else if (mat == 2)  s = w12;
    else               { s = w22; sc = 0.1f; }
    float* dst = wb + (mat + 1) * D * D;

    int tx = threadIdx.x, ty = threadIdx.y;
    int k0 = blockIdx.y * 32, n0 = blockIdx.x * 32;
    #pragma unroll
    for (int j = 0; j < 4; j++)
        tile[ty + j * 8][tx] = s[(size_t)(k0 + ty + j * 8) * D + n0 + tx];
    __syncthreads();
    #pragma unroll
    for (int j = 0; j < 4; j++)
        dst[(size_t)(n0 + ty + j * 8) * D + k0 + tx] = rndtf(tile[tx][ty + j * 8] * sc);
}

// ================= CSR build ==================================================
__global__ void deg_kernel(const int* __restrict__ dst, int* __restrict__ cnt, int E)
{
    int i = blockIdx.x * blockDim.x + threadIdx.x;
    if (i < E) atomicAdd(cnt + __ldg(dst + i), 1);
}

__global__ void scan_kernel(const int* __restrict__ cnt, int* __restrict__ off,
                            int* __restrict__ cur, float* __restrict__ norm, int n)
{
    __shared__ int sh[1024];
    const int CH = 20;
    int t = threadIdx.x;
    int base = t * CH;
    int v[CH];
    if (base + CH <= n) {
        #pragma unroll
        for (int i = 0; i < CH / 4; i++) {
            int4 q = *reinterpret_cast<const int4*>(cnt + base + i * 4);
            v[i * 4 + 0] = q.x; v[i * 4 + 1] = q.y;
            v[i * 4 + 2] = q.z; v[i * 4 + 3] = q.w;
        }
    } else {
        #pragma unroll
        for (int i = 0; i < CH; i++) v[i] = (base + i < n) ? cnt[base + i] : 0;
    }
    int s = 0;
    #pragma unroll
    for (int i = 0; i < CH; i++) s += v[i];
    sh[t] = s;
    __syncthreads();
    for (int d = 1; d < 1024; d <<= 1) {
        int x = (t >= d) ? sh[t - d] : 0;
        __syncthreads();
        sh[t] += x;
        __syncthreads();
    }
    int run = sh[t] - s;
    #pragma unroll
    for (int i = 0; i < CH; i++) {
        int idx = base + i;
        if (idx < n) {
            off[idx] = run;
            cur[idx] = run;
            norm[idx] = rsqrtf(fmaxf((float)v[i], 1.0f));
            run += v[i];
        }
    }
    if (t == 1023) off[n] = sh[1023];
}

__global__ void fill_kernel(const int* __restrict__ src, const int* __restrict__ dst,
                            int* __restrict__ cur, int* __restrict__ csr, int E)
{
    int i = blockIdx.x * blockDim.x + threadIdx.x;
    if (i < E) {
        int d = __ldg(dst + i);
        int p = atomicAdd(cur + d, 1);
        csr[p] = __ldg(src + i);
    }
}

// ================= aggregation: fp16 gather, fp32 accumulate =================
// F[n,:] = rndtf( 0.9 * norm[n] * sum norm[src]*h16[src,:] )
__global__ __launch_bounds__(128)
void agg_kernel(const __half* __restrict__ h, const float* __restrict__ norm,
                const int* __restrict__ off, const int* __restrict__ csr,
                float* __restrict__ F)
{
    int node = blockIdx.x;
    int c    = threadIdx.x * 4;
    int s0 = __ldg(off + node);
    int s1 = __ldg(off + node + 1);
    float4 acc = make_float4(0.f, 0.f, 0.f, 0.f);
    int j = s0;
    for (; j + 3 < s1; j += 4) {
        int   si[4];
        float wi[4];
        #pragma unroll
        for (int u = 0; u < 4; u++) si[u] = __ldg(csr + j + u);
        #pragma unroll
        for (int u = 0; u < 4; u++) wi[u] = __ldg(norm + si[u]);
        uint2 q[4];
        #pragma unroll
        for (int u = 0; u < 4; u++)
            q[u] = *reinterpret_cast<const uint2*>(h + (size_t)si[u] * D + c);
        #pragma unroll
        for (int u = 0; u < 4; u++) {
            float2 lo = __half22float2(*reinterpret_cast<__half2*>(&q[u].x));
            float2 hi = __half22float2(*reinterpret_cast<__half2*>(&q[u].y));
            acc.x += wi[u] * lo.x;
            acc.y += wi[u] * lo.y;
            acc.z += wi[u] * hi.x;
            acc.w += wi[u] * hi.y;
        }
    }
    for (; j < s1; j++) {
        int sA = __ldg(csr + j);
        float wA = __ldg(norm + sA);
        uint2 q = *reinterpret_cast<const uint2*>(h + (size_t)sA * D + c);
        float2 lo = __half22float2(*reinterpret_cast<__half2*>(&q.x));
        float2 hi = __half22float2(*reinterpret_cast<__half2*>(&q.y));
        acc.x += wA * lo.x; acc.y += wA * lo.y;
        acc.z += wA * hi.x; acc.w += wA * hi.y;
    }
    float wn = __ldg(norm + node) * 0.9f;
    float4 r;
    r.x = rndtf(acc.x * wn);
    r.y = rndtf(acc.y * wn);
    r.z = rndtf(acc.z * wn);
    r.w = rndtf(acc.w * wn);
    *reinterpret_cast<float4*>(F + (size_t)node * D + c) = r;
}

// ================= unified tf32 GEMM (cp.async + ldmatrix) ===================
#define STG 3
#define AE 4096

// LAYER=false: out = A0 @ B0^T + bias
// LAYER=true:  out = relu(beta*(A0@B0 + A1@B1) + (1-beta)*(A0 + 0.1*A1) + bias)
// OUT32 -> C fp32;  OUT16 -> C16 fp16 mirror
template <bool LAYER, bool OUT32, bool OUT16>
__global__ __launch_bounds__(256, 2)
void gemm_tc(const float* __restrict__ A0, const float* __restrict__ A1,
             const float* __restrict__ B0, const float* __restrict__ B1,
             const float* __restrict__ bias, float* __restrict__ C,
             __half* __restrict__ C16, int M, float beta)
{
    extern __shared__ unsigned sm[];
    const int tid = threadIdx.x, lane = tid & 31, warp = tid >> 5;
    const int wm = warp >> 2, wn = warp & 3;
    const int bm = blockIdx.y * 128, bn = blockIdx.x * 128;
    const uint32_t smb = (uint32_t)__cvta_generic_to_shared(sm);
    const uint32_t smbB = smb + STG * AE * 4u;

    float acc[4][4][4] = {};

    int lrow[4], lc[4], avalid[4];
    uint32_t dA[4], dB[4];
    #pragma unroll
    for (int i = 0; i < 4; i++) {
        int cid = tid + i * 256;
        lrow[i] = cid >> 3;
        lc[i]   = cid & 7;
        int cs  = lc[i] ^ (lrow[i] & 7);
        dA[i] = smb  + (uint32_t)(lrow[i] * 32 + cs * 4) * 4u;
        dB[i] = dA[i] + STG * AE * 4u;
        avalid[i] = (bm + lrow[i] < M) ? 16 : 0;
    }

    auto issue = [&](int stage, int t) {
        const float* Ap;
        const float* Bp;
        int k0;
        if (LAYER) {
            bool second = (t >= 16);
            Ap = second ? A1 : A0;
            Bp = second ? B1 : B0;
            k0 = (t & 15) * 32;
        } else {
            Ap = A0; Bp = B0; k0 = t * 32;
        }
        uint32_t so = (uint32_t)stage * AE * 4u;
        #pragma unroll
        for (int i = 0; i < 4; i++) {
            const float* as = Ap + (size_t)(avalid[i] ? bm + lrow[i] : 0) * D + k0 + lc[i] * 4;
            cp16(dA[i] + so, as, avalid[i]);
            const float* bs = Bp + (size_t)(bn + lrow[i]) * D + k0 + lc[i] * 4;
            cp16(dB[i] + so, bs, 16);
        }
        cp_commit();
    };

    const int hiA = (lane >> 4) & 1;
    uint32_t abase[4];
    int akey[4];
    #pragma unroll
    for (int mt = 0; mt < 4; mt++) {
        int row = wm * 64 + mt * 16 + (lane & 15);
        akey[mt]  = row & 7;
        abase[mt] = (uint32_t)row * 128u;
    }
    const int hiB = (lane >> 3) & 1;
    uint32_t bbase[2];
    int bkey[2];
    #pragma unroll
    for (int np = 0; np < 2; np++) {
        int row = wn * 32 + np * 16 + (lane & 7) + ((lane & 16) ? 8 : 0);
        bkey[np]  = row & 7;
        bbase[np] = (uint32_t)row * 128u;
    }

    auto compute = [&](int stage) {
        uint32_t sa = smb  + (uint32_t)stage * AE * 4u;
        uint32_t sb = smbB + (uint32_t)stage * AE * 4u;
        #pragma unroll
        for (int kc = 0; kc < 4; kc++) {
            unsigned af[4][4], bf[4][2];
            #pragma unroll
            for (int mt = 0; mt < 4; mt++) {
                uint32_t addr = sa + abase[mt] + (uint32_t)(((2 * kc + hiA) ^ akey[mt]) << 4);
                ldsm4(af[mt][0], af[mt][1], af[mt][2], af[mt][3], addr);
            }
            #pragma unroll
            for (int np = 0; np < 2; np++) {
                uint32_t addr = sb + bbase[np] + (uint32_t)(((2 * kc + hiB) ^ bkey[np]) << 4);
                ldsm4(bf[2 * np][0], bf[2 * np][1], bf[2 * np + 1][0], bf[2 * np + 1][1], addr);
            }
            #pragma unroll
            for (int mt = 0; mt < 4; mt++)
                #pragma unroll
                for (int nt = 0; nt < 4; nt++)
                    mma8(acc[mt][nt], af[mt][0], af[mt][1], af[mt][2], af[mt][3],
                         bf[nt][0], bf[nt][1]);
        }
    };

    const int T = LAYER ? 32 : 16;
    issue(0, 0);
    issue(1, 1);
    for (int t = 0; t < T; t++) {
        cp_wait<STG - 2>();
        __syncthreads();
        if (t + STG - 1 < T) issue((t + STG - 1) % STG, t + STG - 1);
        else                 cp_commit();
        compute(t % STG);
    }

    const int grp = lane >> 2, tig = lane & 3;
    const float ob = 1.0f - beta;
    #pragma unroll
    for (int mt = 0; mt < 4; mt++) {
        int gr[2];
        gr[0] = bm + wm * 64 + mt * 16 + grp;
        gr[1] = gr[0] + 8;
        #pragma unroll
        for (int nt = 0; nt < 4; nt++) {
            int gc = bn + wn * 32 + nt * 8 + tig * 2;
            float2 bb = *reinterpret_cast<const float2*>(bias + gc);
            #pragma unroll
            for (int hh = 0; hh < 2; hh++) {
                if (gr[hh] >= M) continue;
                size_t base = (size_t)gr[hh] * D + gc;
                float2 v;
                if (LAYER) {
                    float2 f  = *reinterpret_cast<const float2*>(A0 + base);
                    float2 h0 = *reinterpret_cast<const float2*>(A1 + base);
                    v.x = fmaxf(beta * acc[mt][nt][2 * hh + 0] + ob * (f.x + 0.1f * h0.x) + bb.x, 0.f);
                    v.y = fmaxf(beta * acc[mt][nt][2 * hh + 1] + ob * (f.y + 0.1f * h0.y) + bb.y, 0.f);
                } else {
                    v.x = acc[mt][nt][2 * hh + 0] + bb.x;
                    v.y = acc[mt][nt][2 * hh + 1] + bb.y;
                }
                if (OUT32)
                    *reinterpret_cast<float2*>(C + base) = v;
                if (OUT16)
                    *reinterpret_cast<__half2*>(C16 + base) = __floats2half2_rn(v.x, v.y);
            }
        }
    }
}

// ================= host orchestration =========================================
extern "C" void kernel_launch(void* const* d_in, const int* in_sizes, int n_in,
                              void* d_out, int out_size)
{
    const float* feat = (const float*)d_in[0];
    const int*   src  = (const int*)  d_in[1];
    const int*   dst  = (const int*)  d_in[2];
    const float* fc_w = (const float*)d_in[3];
    const float* fc_b = (const float*)d_in[4];
    const float* w1_1 = (const float*)d_in[5];
    const float* w2_1 = (const float*)d_in[6];
    const float* b_1  = (const float*)d_in[7];
    const float* w1_2 = (const float*)d_in[8];
    const float* w2_2 = (const float*)d_in[9];
    const float* b_2  = (const float*)d_in[10];
    float* out = (float*)d_out;

    int M = in_sizes[0] / D;
    int E = in_sizes[1];

    float *H, *F, *WB, *NORM;
    __half *H16, *R16;
    int *CNT, *OFF, *CUR, *CSR;
    cudaGetSymbolAddress((void**)&H,    g_H);
    cudaGetSymbolAddress((void**)&F,    g_F);
    cudaGetSymbolAddress((void**)&H16,  g_H16);
    cudaGetSymbolAddress((void**)&R16,  g_R16);
    cudaGetSymbolAddress((void**)&WB,   g_WB);
    cudaGetSymbolAddress((void**)&NORM, g_norm);
    cudaGetSymbolAddress((void**)&CNT,  g_cnt);
    cudaGetSymbolAddress((void**)&OFF,  g_off);
    cudaGetSymbolAddress((void**)&CUR,  g_cur);
    cudaGetSymbolAddress((void**)&CSR,  g_csr);

    const int smem = STG * AE * 2 * 4;   // 98304
    cudaFuncSetAttribute((const void*)gemm_tc<false, true,  true >, cudaFuncAttributeMaxDynamicSharedMemorySize, smem);
    cudaFuncSetAttribute((const void*)gemm_tc<true,  false, true >, cudaFuncAttributeMaxDynamicSharedMemorySize, smem);
    cudaFuncSetAttribute((const void*)gemm_tc<true,  true,  false>, cudaFuncAttributeMaxDynamicSharedMemorySize, smem);

    dim3 grid(D / 128, (M + 127) / 128);

    // ---- fork: CSR chain on side stream, prep+fc GEMM on main ----
    cudaEventRecord(g_ss.evF, 0);
    cudaStreamWaitEvent(g_ss.s2, g_ss.evF, 0);

    cudaMemsetAsync(CNT, 0, (size_t)M * sizeof(int), g_ss.s2);
    deg_kernel <<<(E + 255) / 256, 256, 0, g_ss.s2>>>(dst, CNT, E);
    scan_kernel<<<1, 1024, 0, g_ss.s2>>>(CNT, OFF, CUR, NORM, M);
    fill_kernel<<<(E + 255) / 256, 256, 0, g_ss.s2>>>(src, dst, CUR, CSR, E);

    prep_fc<<<(D * D + 255) / 256, 256>>>(fc_w, WB);
    prep_wT<<<dim3(16, 16, 4), dim3(32, 8)>>>(w1_1, w2_1, w1_2, w2_2, WB);
    gemm_tc<false, true, true><<<grid, 256, smem>>>(feat, nullptr, WB, nullptr,
                                                    fc_b, H, H16, M, 0.f);

    cudaEventRecord(g_ss.evJ, g_ss.s2);
    cudaStreamWaitEvent(0, g_ss.evJ, 0);
    // ---- join ----

    const float beta1 = logf(2.0f);
    const float beta2 = logf(1.5f);

    agg_kernel<<<M, 128>>>(H16, NORM, OFF, CSR, F);
    gemm_tc<true, false, true><<<grid, 256, smem>>>(F, H, WB + 1 * D * D, WB + 2 * D * D,
                                                    b_1, nullptr, R16, M, beta1);

    agg_kernel<<<M, 128>>>(R16, NORM, OFF, CSR, F);
    gemm_tc<true, true, false><<<grid, 256, smem>>>(F, H, WB + 3 * D * D, WB + 4 * D * D,
                                                    b_2, out, nullptr, M, beta2);
}

// round 10
// speedup vs baseline: 1.3970x; 1.3970x over previous
#include <cuda_runtime.h>
#include <cuda_fp16.h>
#include <cstdint>
#include <math.h>

#define NMAX 20000
#define EMAX 320000
#define D 512

// ---------------- scratch (static device globals; no allocation) -------------
__device__ float  g_H  [NMAX * D];
__device__ float  g_F  [NMAX * D];
__device__ __half g_H16[NMAX * D];
__device__ __half g_R16[NMAX * D];
__device__ float  g_WB [5 * D * D];     // tf32-rounded weights, ALL [N][K] K-major
__device__ float  g_norm[NMAX];
__device__ int    g_cnt [NMAX];
__device__ int    g_off [NMAX + 1];
__device__ int    g_cur [NMAX + 1];
__device__ int    g_csr [EMAX];

// ================= small helpers ==============================================
__device__ __forceinline__ unsigned f2tf(float x)
{
    unsigned r;
    asm("cvt.rna.tf32.f32 %0, %1;" : "=r"(r) : "f"(x));
    return r;
}
__device__ __forceinline__ float rndtf(float x) { return __uint_as_float(f2tf(x)); }

__device__ __forceinline__ void cp16(uint32_t dst, const float* src, int bytes)
{
    asm volatile("cp.async.cg.shared.global [%0], [%1], 16, %2;"
                 :: "r"(dst), "l"(src), "r"(bytes));
}
__device__ __forceinline__ void cp_commit() { asm volatile("cp.async.commit_group;"); }
template <int N> __device__ __forceinline__ void cp_wait()
{ asm volatile("cp.async.wait_group %0;" :: "n"(N)); }

__device__ __forceinline__ void mma8(float* c,
                                     unsigned a0, unsigned a1, unsigned a2, unsigned a3,
                                     unsigned b0, unsigned b1)
{
    asm volatile(
        "mma.sync.aligned.m16n8k8.row.col.f32.tf32.tf32.f32 "
        "{%0,%1,%2,%3},{%4,%5,%6,%7},{%8,%9},{%0,%1,%2,%3};"
        : "+f"(c[0]), "+f"(c[1]), "+f"(c[2]), "+f"(c[3])
        : "r"(a0), "r"(a1), "r"(a2), "r"(a3), "r"(b0), "r"(b1));
}

__device__ __forceinline__ void ldsm4(unsigned& r0, unsigned& r1, unsigned& r2, unsigned& r3,
                                      uint32_t addr)
{
    asm volatile("ldmatrix.sync.aligned.m8n8.x4.shared.b16 {%0,%1,%2,%3}, [%4];"
                 : "=r"(r0), "=r"(r1), "=r"(r2), "=r"(r3) : "r"(addr));
}

// ================= weight prep ===============================================
__global__ void prep_fc(const float* __restrict__ fcw, float* __restrict__ wb)
{
    int i = blockIdx.x * blockDim.x + threadIdx.x;
    if (i < D * D) wb[i] = rndtf(fcw[i]);
}

__global__ void prep_wT(const float* __restrict__ w11, const float* __restrict__ w21,
                        const float* __restrict__ w12, const float* __restrict__ w22,
                        float* __restrict__ wb)
{
    __shared__ float tile[32][33];
    int mat = blockIdx.z;
    const float* s;
    float sc = 1.0f;
    if      (mat == 0)  s = w11;
    else if (mat == 1) { s = w21; sc = 0.1f; }
    else if (mat == 2)  s = w12;
    else               { s = w22; sc = 0.1f; }
    float* dst = wb + (mat + 1) * D * D;

    int tx = threadIdx.x, ty = threadIdx.y;
    int k0 = blockIdx.y * 32, n0 = blockIdx.x * 32;
    #pragma unroll
    for (int j = 0; j < 4; j++)
        tile[ty + j * 8][tx] = s[(size_t)(k0 + ty + j * 8) * D + n0 + tx];
    __syncthreads();
    #pragma unroll
    for (int j = 0; j < 4; j++)
        dst[(size_t)(n0 + ty + j * 8) * D + k0 + tx] = rndtf(tile[tx][ty + j * 8] * sc);
}

// ================= CSR build ==================================================
__global__ void deg_kernel(const int* __restrict__ dst, int* __restrict__ cnt, int E)
{
    int i = blockIdx.x * blockDim.x + threadIdx.x;
    if (i < E) atomicAdd(cnt + __ldg(dst + i), 1);
}

__global__ void scan_kernel(const int* __restrict__ cnt, int* __restrict__ off,
                            int* __restrict__ cur, float* __restrict__ norm, int n)
{
    __shared__ int sh[1024];
    const int CH = 20;
    int t = threadIdx.x;
    int base = t * CH;
    int v[CH];
    if (base + CH <= n) {
        #pragma unroll
        for (int i = 0; i < CH / 4; i++) {
            int4 q = *reinterpret_cast<const int4*>(cnt + base + i * 4);
            v[i * 4 + 0] = q.x; v[i * 4 + 1] = q.y;
            v[i * 4 + 2] = q.z; v[i * 4 + 3] = q.w;
        }
    } else {
        #pragma unroll
        for (int i = 0; i < CH; i++) v[i] = (base + i < n) ? cnt[base + i] : 0;
    }
    int s = 0;
    #pragma unroll
    for (int i = 0; i < CH; i++) s += v[i];
    sh[t] = s;
    __syncthreads();
    for (int d = 1; d < 1024; d <<= 1) {
        int x = (t >= d) ? sh[t - d] : 0;
        __syncthreads();
        sh[t] += x;
        __syncthreads();
    }
    int run = sh[t] - s;
    #pragma unroll
    for (int i = 0; i < CH; i++) {
        int idx = base + i;
        if (idx < n) {
            off[idx] = run;
            cur[idx] = run;
            norm[idx] = rsqrtf(fmaxf((float)v[i], 1.0f));
            run += v[i];
        }
    }
    if (t == 1023) off[n] = sh[1023];
}

__global__ void fill_kernel(const int* __restrict__ src, const int* __restrict__ dst,
                            int* __restrict__ cur, int* __restrict__ csr, int E)
{
    int i = blockIdx.x * blockDim.x + threadIdx.x;
    if (i < E) {
        int d = __ldg(dst + i);
        int p = atomicAdd(cur + d, 1);
        csr[p] = __ldg(src + i);
    }
}

// ================= aggregation: fp16 gather, fp32 accumulate =================
// F[n,:] = rndtf( 0.9 * norm[n] * sum norm[src]*h16[src,:] )
__global__ __launch_bounds__(128)
void agg_kernel(const __half* __restrict__ h, const float* __restrict__ norm,
                const int* __restrict__ off, const int* __restrict__ csr,
                float* __restrict__ F)
{
    int node = blockIdx.x;
    int c    = threadIdx.x * 4;
    int s0 = __ldg(off + node);
    int s1 = __ldg(off + node + 1);
    float4 acc = make_float4(0.f, 0.f, 0.f, 0.f);
    int j = s0;
    for (; j + 3 < s1; j += 4) {
        int   si[4];
        float wi[4];
        #pragma unroll
        for (int u = 0; u < 4; u++) si[u] = __ldg(csr + j + u);
        #pragma unroll
        for (int u = 0; u < 4; u++) wi[u] = __ldg(norm + si[u]);
        uint2 q[4];
        #pragma unroll
        for (int u = 0; u < 4; u++)
            q[u] = *reinterpret_cast<const uint2*>(h + (size_t)si[u] * D + c);
        #pragma unroll
        for (int u = 0; u < 4; u++) {
            float2 lo = __half22float2(*reinterpret_cast<__half2*>(&q[u].x));
            float2 hi = __half22float2(*reinterpret_cast<__half2*>(&q[u].y));
            acc.x += wi[u] * lo.x;
            acc.y += wi[u] * lo.y;
            acc.z += wi[u] * hi.x;
            acc.w += wi[u] * hi.y;
        }
    }
    for (; j < s1; j++) {
        int sA = __ldg(csr + j);
        float wA = __ldg(norm + sA);
        uint2 q = *reinterpret_cast<const uint2*>(h + (size_t)sA * D + c);
        float2 lo = __half22float2(*reinterpret_cast<__half2*>(&q.x));
        float2 hi = __half22float2(*reinterpret_cast<__half2*>(&q.y));
        acc.x += wA * lo.x; acc.y += wA * lo.y;
        acc.z += wA * hi.x; acc.w += wA * hi.y;
    }
    float wn = __ldg(norm + node) * 0.9f;
    float4 r;
    r.x = rndtf(acc.x * wn);
    r.y = rndtf(acc.y * wn);
    r.z = rndtf(acc.z * wn);
    r.w = rndtf(acc.w * wn);
    *reinterpret_cast<float4*>(F + (size_t)node * D + c) = r;
}

// ================= unified tf32 GEMM (cp.async + ldmatrix) ===================
#define STG 3
#define AE 4096

// LAYER=false: out = A0 @ B0^T + bias
// LAYER=true:  out = relu(beta*(A0@B0 + A1@B1) + (1-beta)*(A0 + 0.1*A1) + bias)
// OUT32 -> C fp32;  OUT16 -> C16 fp16 mirror
template <bool LAYER, bool OUT32, bool OUT16>
__global__ __launch_bounds__(256, 2)
void gemm_tc(const float* __restrict__ A0, const float* __restrict__ A1,
             const float* __restrict__ B0, const float* __restrict__ B1,
             const float* __restrict__ bias, float* __restrict__ C,
             __half* __restrict__ C16, int M, float beta)
{
    extern __shared__ unsigned sm[];
    const int tid = threadIdx.x, lane = tid & 31, warp = tid >> 5;
    const int wm = warp >> 2, wn = warp & 3;
    const int bm = blockIdx.y * 128, bn = blockIdx.x * 128;
    const uint32_t smb = (uint32_t)__cvta_generic_to_shared(sm);
    const uint32_t smbB = smb + STG * AE * 4u;

    float acc[4][4][4] = {};

    int lrow[4], lc[4], avalid[4];
    uint32_t dA[4], dB[4];
    #pragma unroll
    for (int i = 0; i < 4; i++) {
        int cid = tid + i * 256;
        lrow[i] = cid >> 3;
        lc[i]   = cid & 7;
        int cs  = lc[i] ^ (lrow[i] & 7);
        dA[i] = smb  + (uint32_t)(lrow[i] * 32 + cs * 4) * 4u;
        dB[i] = dA[i] + STG * AE * 4u;
        avalid[i] = (bm + lrow[i] < M) ? 16 : 0;
    }

    auto issue = [&](int stage, int t) {
        const float* Ap;
        const float* Bp;
        int k0;
        if (LAYER) {
            bool second = (t >= 16);
            Ap = second ? A1 : A0;
            Bp = second ? B1 : B0;
            k0 = (t & 15) * 32;
        } else {
            Ap = A0; Bp = B0; k0 = t * 32;
        }
        uint32_t so = (uint32_t)stage * AE * 4u;
        #pragma unroll
        for (int i = 0; i < 4; i++) {
            const float* as = Ap + (size_t)(avalid[i] ? bm + lrow[i] : 0) * D + k0 + lc[i] * 4;
            cp16(dA[i] + so, as, avalid[i]);
            const float* bs = Bp + (size_t)(bn + lrow[i]) * D + k0 + lc[i] * 4;
            cp16(dB[i] + so, bs, 16);
        }
        cp_commit();
    };

    const int hiA = (lane >> 4) & 1;
    uint32_t abase[4];
    int akey[4];
    #pragma unroll
    for (int mt = 0; mt < 4; mt++) {
        int row = wm * 64 + mt * 16 + (lane & 15);
        akey[mt]  = row & 7;
        abase[mt] = (uint32_t)row * 128u;
    }
    const int hiB = (lane >> 3) & 1;
    uint32_t bbase[2];
    int bkey[2];
    #pragma unroll
    for (int np = 0; np < 2; np++) {
        int row = wn * 32 + np * 16 + (lane & 7) + ((lane & 16) ? 8 : 0);
        bkey[np]  = row & 7;
        bbase[np] = (uint32_t)row * 128u;
    }

    auto compute = [&](int stage) {
        uint32_t sa = smb  + (uint32_t)stage * AE * 4u;
        uint32_t sb = smbB + (uint32_t)stage * AE * 4u;
        #pragma unroll
        for (int kc = 0; kc < 4; kc++) {
            unsigned af[4][4], bf[4][2];
            #pragma unroll
            for (int mt = 0; mt < 4; mt++) {
                uint32_t addr = sa + abase[mt] + (uint32_t)(((2 * kc + hiA) ^ akey[mt]) << 4);
                ldsm4(af[mt][0], af[mt][1], af[mt][2], af[mt][3], addr);
            }
            #pragma unroll
            for (int np = 0; np < 2; np++) {
                uint32_t addr = sb + bbase[np] + (uint32_t)(((2 * kc + hiB) ^ bkey[np]) << 4);
                ldsm4(bf[2 * np][0], bf[2 * np][1], bf[2 * np + 1][0], bf[2 * np + 1][1], addr);
            }
            #pragma unroll
            for (int mt = 0; mt < 4; mt++)
                #pragma unroll
                for (int nt = 0; nt < 4; nt++)
                    mma8(acc[mt][nt], af[mt][0], af[mt][1], af[mt][2], af[mt][3],
                         bf[nt][0], bf[nt][1]);
        }
    };

    const int T = LAYER ? 32 : 16;
    issue(0, 0);
    issue(1, 1);
    for (int t = 0; t < T; t++) {
        cp_wait<STG - 2>();
        __syncthreads();
        if (t + STG - 1 < T) issue((t + STG - 1) % STG, t + STG - 1);
        else                 cp_commit();
        compute(t % STG);
    }

    const int grp = lane >> 2, tig = lane & 3;
    const float ob = 1.0f - beta;
    #pragma unroll
    for (int mt = 0; mt < 4; mt++) {
        int gr[2];
        gr[0] = bm + wm * 64 + mt * 16 + grp;
        gr[1] = gr[0] + 8;
        #pragma unroll
        for (int nt = 0; nt < 4; nt++) {
            int gc = bn + wn * 32 + nt * 8 + tig * 2;
            float2 bb = *reinterpret_cast<const float2*>(bias + gc);
            #pragma unroll
            for (int hh = 0; hh < 2; hh++) {
                if (gr[hh] >= M) continue;
                size_t base = (size_t)gr[hh] * D + gc;
                float2 v;
                if (LAYER) {
                    float2 f  = *reinterpret_cast<const float2*>(A0 + base);
                    float2 h0 = *reinterpret_cast<const float2*>(A1 + base);
                    v.x = fmaxf(beta * acc[mt][nt][2 * hh + 0] + ob * (f.x + 0.1f * h0.x) + bb.x, 0.f);
                    v.y = fmaxf(beta * acc[mt][nt][2 * hh + 1] + ob * (f.y + 0.1f * h0.y) + bb.y, 0.f);
                } else {
                    v.x = acc[mt][nt][2 * hh + 0] + bb.x;
                    v.y = acc[mt][nt][2 * hh + 1] + bb.y;
                }
                if (OUT32)
                    *reinterpret_cast<float2*>(C + base) = v;
                if (OUT16)
                    *reinterpret_cast<__half2*>(C16 + base) = __floats2half2_rn(v.x, v.y);
            }
        }
    }
}

// ================= host orchestration =========================================
extern "C" void kernel_launch(void* const* d_in, const int* in_sizes, int n_in,
                              void* d_out, int out_size)
{
    const float* feat = (const float*)d_in[0];
    const int*   src  = (const int*)  d_in[1];
    const int*   dst  = (const int*)  d_in[2];
    const float* fc_w = (const float*)d_in[3];
    const float* fc_b = (const float*)d_in[4];
    const float* w1_1 = (const float*)d_in[5];
    const float* w2_1 = (const float*)d_in[6];
    const float* b_1  = (const float*)d_in[7];
    const float* w1_2 = (const float*)d_in[8];
    const float* w2_2 = (const float*)d_in[9];
    const float* b_2  = (const float*)d_in[10];
    float* out = (float*)d_out;

    int M = in_sizes[0] / D;
    int E = in_sizes[1];

    float *H, *F, *WB, *NORM;
    __half *H16, *R16;
    int *CNT, *OFF, *CUR, *CSR;
    cudaGetSymbolAddress((void**)&H,    g_H);
    cudaGetSymbolAddress((void**)&F,    g_F);
    cudaGetSymbolAddress((void**)&H16,  g_H16);
    cudaGetSymbolAddress((void**)&R16,  g_R16);
    cudaGetSymbolAddress((void**)&WB,   g_WB);
    cudaGetSymbolAddress((void**)&NORM, g_norm);
    cudaGetSymbolAddress((void**)&CNT,  g_cnt);
    cudaGetSymbolAddress((void**)&OFF,  g_off);
    cudaGetSymbolAddress((void**)&CUR,  g_cur);
    cudaGetSymbolAddress((void**)&CSR,  g_csr);

    const int smem = STG * AE * 2 * 4;   // 98304
    cudaFuncSetAttribute((const void*)gemm_tc<false, true,  true >, cudaFuncAttributeMaxDynamicSharedMemorySize, smem);
    cudaFuncSetAttribute((const void*)gemm_tc<true,  false, true >, cudaFuncAttributeMaxDynamicSharedMemorySize, smem);
    cudaFuncSetAttribute((const void*)gemm_tc<true,  true,  false>, cudaFuncAttributeMaxDynamicSharedMemorySize, smem);

    dim3 grid(D / 128, (M + 127) / 128);

    cudaMemsetAsync(CNT, 0, (size_t)M * sizeof(int));
    deg_kernel<<<(E + 255) / 256, 256>>>(dst, CNT, E);
    prep_fc<<<(D * D + 255) / 256, 256>>>(fc_w, WB);
    prep_wT<<<dim3(16, 16, 4), dim3(32, 8)>>>(w1_1, w2_1, w1_2, w2_2, WB);
    scan_kernel<<<1, 1024>>>(CNT, OFF, CUR, NORM, M);

    gemm_tc<false, true, true><<<grid, 256, smem>>>(feat, nullptr, WB, nullptr,
                                                    fc_b, H, H16, M, 0.f);

    fill_kernel<<<(E + 255) / 256, 256>>>(src, dst, CUR, CSR, E);

    const float beta1 = logf(2.0f);
    const float beta2 = logf(1.5f);

    agg_kernel<<<M, 128>>>(H16, NORM, OFF, CSR, F);
    gemm_tc<true, false, true><<<grid, 256, smem>>>(F, H, WB + 1 * D * D, WB + 2 * D * D,
                                                    b_1, nullptr, R16, M, beta1);

    agg_kernel<<<M, 128>>>(R16, NORM, OFF, CSR, F);
    gemm_tc<true, true, false><<<grid, 256, smem>>>(F, H, WB + 3 * D * D, WB + 4 * D * D,
                                                    b_2, out, nullptr, M, beta2);
}